// round 3
// baseline (speedup 1.0000x reference)
#include <cuda_runtime.h>
#include <math.h>

// Problem constants
#define BB 64
#define HH 1024
#define EE 512
#define VV 32000
#define TENC 64
#define STEPS 32
#define KOUT 2048   // 2*H

// ---------------- scratch (device globals; no allocation allowed) ----------
__device__ float g_a0[BB * 192];        // [latent | style_emb]
__device__ float g_h[BB * HH];          // hidden state
__device__ float g_x[BB * EE];          // current input embedding
__device__ float g_vcat[BB * KOUT];     // [h_new | ctx]
__device__ float g_gi[BB * 3 * HH];     // x @ W_ih^T + b_ih
__device__ float g_gh[BB * 3 * HH];     // h @ W_hh^T + b_hh
__device__ float g_q[BB * HH];          // h_new @ W_a

typedef unsigned long long ull;

__device__ __forceinline__ ull pack2(float x, float y) {
    ull r; asm("mov.b64 %0, {%1, %2};" : "=l"(r) : "f"(x), "f"(y)); return r;
}
__device__ __forceinline__ void fma2(ull &d, ull a, ull b) {
    asm("fma.rn.f32x2 %0, %1, %2, %0;" : "+l"(d) : "l"(a), "l"(b));
}
__device__ __forceinline__ float2 unpack2(ull v) {
    float lo, hi; asm("mov.b64 {%0, %1}, %2;" : "=f"(lo), "=f"(hi) : "l"(v));
    float2 f; f.x = lo; f.y = hi; return f;
}

// ---------------------------------------------------------------------------
// Generic M=64 GEMM: C[64,N] = A[64,K] @ B (+bias)
//   BT=false: B is [K,N] row-major (W_l2h, W_a, W_out)
//   BT=true : B is [N,K] row-major (W_ih, W_hh) -> C = A @ B^T
// Tile: 64m x 128n, KT=16, 128 threads, 8x8 per thread via fp32x2 FFMA2.
// Requires: N % 128 == 0, K % 16 == 0 (all shapes here satisfy this).
// ---------------------------------------------------------------------------
template <bool BT>
__global__ __launch_bounds__(128)
void gemm64(const float* __restrict__ A, int lda,
            const float* __restrict__ Bm,
            const float* __restrict__ bias,
            float* __restrict__ C, long ldc,
            int N, int K)
{
    __shared__ float As[16][68];    // padded: 2-way max conflict
    __shared__ float Bs[16][132];   // padded

    const int tid = threadIdx.x;
    const int n0  = blockIdx.x * 128;
    const int tm  = (tid >> 4) << 3;   // 0..56
    const int tn  = (tid & 15) << 3;   // 0..120

    ull acc[8][4];
#pragma unroll
    for (int i = 0; i < 8; i++)
#pragma unroll
        for (int j = 0; j < 4; j++) acc[i][j] = pack2(0.f, 0.f);

    for (int k0 = 0; k0 < K; k0 += 16) {
        // load A tile: 64 rows x 16 k (coalesced over k)
        {
            int k = tid & 15, m = tid >> 4;
#pragma unroll
            for (int i = 0; i < 8; i++)
                As[k][m + i * 8] = A[(m + i * 8) * lda + k0 + k];
        }
        // load B tile
        if (!BT) {
            int w = tid >> 5, n4 = (tid & 31) << 2;
#pragma unroll
            for (int kb = 0; kb < 4; kb++) {
                int k = kb * 4 + w;
                *reinterpret_cast<float4*>(&Bs[k][n4]) =
                    *reinterpret_cast<const float4*>(&Bm[(size_t)(k0 + k) * N + n0 + n4]);
            }
        } else {
            int k = tid & 15, n = tid >> 4;
#pragma unroll
            for (int i = 0; i < 16; i++)
                Bs[k][n + i * 8] = Bm[(size_t)(n0 + n + i * 8) * K + k0 + k];
        }
        __syncthreads();

#pragma unroll
        for (int kk = 0; kk < 16; kk++) {
            float4 a0 = *reinterpret_cast<const float4*>(&As[kk][tm]);
            float4 a1 = *reinterpret_cast<const float4*>(&As[kk][tm + 4]);
            ulonglong2 bl0 = *reinterpret_cast<const ulonglong2*>(&Bs[kk][tn]);
            ulonglong2 bl1 = *reinterpret_cast<const ulonglong2*>(&Bs[kk][tn + 4]);
            ull b2[4] = { bl0.x, bl0.y, bl1.x, bl1.y };
            float av[8] = { a0.x, a0.y, a0.z, a0.w, a1.x, a1.y, a1.z, a1.w };
#pragma unroll
            for (int i = 0; i < 8; i++) {
                ull ap = pack2(av[i], av[i]);
#pragma unroll
                for (int j = 0; j < 4; j++) fma2(acc[i][j], ap, b2[j]);
            }
        }
        __syncthreads();
    }

#pragma unroll
    for (int i = 0; i < 8; i++) {
        long m = tm + i;
#pragma unroll
        for (int j = 0; j < 4; j++) {
            float2 v = unpack2(acc[i][j]);
            int n = n0 + tn + 2 * j;
            float c0 = v.x, c1 = v.y;
            if (bias) { c0 += bias[n]; c1 += bias[n + 1]; }
            C[m * ldc + n]     = c0;
            C[m * ldc + n + 1] = c1;
        }
    }
}

// ---------------------------------------------------------------------------
__global__ void build_a0(const float* __restrict__ latent,
                         const int* __restrict__ style,
                         const float* __restrict__ style_emb)
{
    int idx = blockIdx.x * blockDim.x + threadIdx.x;   // 64*192
    if (idx >= BB * 192) return;
    int b = idx / 192, k = idx - b * 192;
    g_a0[idx] = (k < 128) ? latent[b * 128 + k]
                          : style_emb[style[b] * 64 + (k - 128)];
}

__global__ void init_x0(const float* __restrict__ emb)
{
    int idx = blockIdx.x * blockDim.x + threadIdx.x;   // 64*512
    g_x[idx] = emb[EE /* BOS=1 row */ + (idx & (EE - 1))];
}

// GRU gates: h_new = (1-z)*n + z*h  (torch gate order r,z,n)
__global__ void gru_gates()
{
    int idx = blockIdx.x * blockDim.x + threadIdx.x;   // 64*1024
    int b = idx >> 10, j = idx & 1023;
    int base = b * 3 * HH + j;
    float ir = g_gi[base], iz = g_gi[base + HH], in = g_gi[base + 2 * HH];
    float hr = g_gh[base], hz = g_gh[base + HH], hn = g_gh[base + 2 * HH];
    float r = 1.f / (1.f + expf(-(ir + hr)));
    float z = 1.f / (1.f + expf(-(iz + hz)));
    float n = tanhf(in + r * hn);
    float h = g_h[idx];
    float hnew = (1.f - z) * n + z * h;
    g_h[idx] = hnew;
    g_vcat[b * KOUT + j] = hnew;
}

// Attention: scores[b,t] = q[b]·enc[b,t,:]; softmax; ctx -> g_vcat[:,1024:]
__global__ void attn_kernel(const float* __restrict__ enc)
{
    int b = blockIdx.x;
    int tid = threadIdx.x;              // 256
    __shared__ float s_q[HH];
    __shared__ float s_scores[TENC];
    __shared__ float s_attn[TENC];

    for (int i = tid; i < HH; i += 256) s_q[i] = g_q[b * HH + i];
    __syncthreads();

    int warp = tid >> 5, lane = tid & 31;
    for (int t = warp; t < TENC; t += 8) {
        const float* e = enc + ((size_t)b * TENC + t) * HH;
        float s = 0.f;
        for (int h = lane; h < HH; h += 32) s += s_q[h] * e[h];
#pragma unroll
        for (int o = 16; o; o >>= 1) s += __shfl_xor_sync(0xFFFFFFFFu, s, o);
        if (lane == 0) s_scores[t] = s;
    }
    __syncthreads();

    float mx = -1e30f;
    for (int t = 0; t < TENC; t++) mx = fmaxf(mx, s_scores[t]);
    if (tid < TENC) s_attn[tid] = expf(s_scores[tid] - mx);
    __syncthreads();
    float ssum = 0.f;
    for (int t = 0; t < TENC; t++) ssum += s_attn[t];
    float inv = 1.f / ssum;

    for (int h = tid; h < HH; h += 256) {
        float c = 0.f;
        const float* eb = enc + (size_t)b * TENC * HH + h;
        for (int t = 0; t < TENC; t++) c += s_attn[t] * eb[(size_t)t * HH];
        g_vcat[b * KOUT + HH + h] = c * inv;
    }
}

// argmax over V + gather embedding of winning token into g_x
__global__ void argmax_embed(const float* __restrict__ logits_t,
                             const float* __restrict__ emb)
{
    int b = blockIdx.x;
    int tid = threadIdx.x;              // 256
    const float* L = logits_t + (size_t)b * STEPS * VV;

    float best = -1e30f; int bi = VV;
    for (int n = tid; n < VV; n += 256) {
        float v = L[n];
        if (v > best) { best = v; bi = n; }
    }
    __shared__ float sv[256]; __shared__ int si[256];
    sv[tid] = best; si[tid] = bi;
    __syncthreads();
    for (int s = 128; s; s >>= 1) {
        if (tid < s) {
            if (sv[tid + s] > sv[tid] ||
                (sv[tid + s] == sv[tid] && si[tid + s] < si[tid])) {
                sv[tid] = sv[tid + s]; si[tid] = si[tid + s];
            }
        }
        __syncthreads();
    }
    int tok = si[0];
    for (int e = tid; e < EE; e += 256)
        g_x[b * EE + e] = emb[(size_t)tok * EE + e];
}

// ---------------------------------------------------------------------------
extern "C" void kernel_launch(void* const* d_in, const int* in_sizes, int n_in,
                              void* d_out, int out_size)
{
    const float* latent    = (const float*)d_in[0];
    const int*   style     = (const int*)  d_in[1];
    const float* enc       = (const float*)d_in[2];
    // d_in[3] = max_length scalar (known: 32)
    const float* emb       = (const float*)d_in[4];
    const float* style_emb = (const float*)d_in[5];
    const float* W_l2h     = (const float*)d_in[6];
    const float* b_l2h     = (const float*)d_in[7];
    const float* W_ih      = (const float*)d_in[8];
    const float* W_hh      = (const float*)d_in[9];
    const float* b_ih      = (const float*)d_in[10];
    const float* b_hh      = (const float*)d_in[11];
    const float* W_a       = (const float*)d_in[12];
    const float* W_out     = (const float*)d_in[13];
    const float* b_out     = (const float*)d_in[14];
    float* out = (float*)d_out;

    float *p_a0, *p_h, *p_x, *p_vcat, *p_gi, *p_gh, *p_q;
    cudaGetSymbolAddress((void**)&p_a0,   g_a0);
    cudaGetSymbolAddress((void**)&p_h,    g_h);
    cudaGetSymbolAddress((void**)&p_x,    g_x);
    cudaGetSymbolAddress((void**)&p_vcat, g_vcat);
    cudaGetSymbolAddress((void**)&p_gi,   g_gi);
    cudaGetSymbolAddress((void**)&p_gh,   g_gh);
    cudaGetSymbolAddress((void**)&p_q,    g_q);

    // init: a0 = [latent | style_emb[style]];  h = a0 @ W_l2h + b;  x = emb[BOS]
    build_a0<<<(BB * 192 + 255) / 256, 256>>>(latent, style, style_emb);
    init_x0<<<(BB * EE + 255) / 256, 256>>>(emb);
    gemm64<false><<<HH / 128, 128>>>(p_a0, 192, W_l2h, b_l2h, p_h, HH, HH, 192);

    for (int t = 0; t < STEPS; t++) {
        // GRU input/hidden projections
        gemm64<true><<<3 * HH / 128, 128>>>(p_x, EE, W_ih, b_ih, p_gi, 3 * HH, 3 * HH, EE);
        gemm64<true><<<3 * HH / 128, 128>>>(p_h, HH, W_hh, b_hh, p_gh, 3 * HH, 3 * HH, HH);
        gru_gates<<<(BB * HH) / 256, 256>>>();
        // q = h_new @ W_a  (refactored Luong attention)
        gemm64<false><<<HH / 128, 128>>>(p_h, HH, W_a, nullptr, p_q, HH, HH, HH);
        attn_kernel<<<BB, 256>>>(enc);
        // logits -> directly into out[b, t, :]
        gemm64<false><<<VV / 128, 128>>>(p_vcat, KOUT, W_out, b_out,
                                         out + (size_t)t * VV, (long)STEPS * VV,
                                         VV, KOUT);
        if (t < STEPS - 1) argmax_embed<<<BB, 256>>>(out + (size_t)t * VV, emb);
    }
}

// round 5
// speedup vs baseline: 2.5090x; 2.5090x over previous
#include <cuda_runtime.h>
#include <cuda_bf16.h>
#include <math.h>

// Problem constants
#define BB 64
#define HH 1024
#define EE 512
#define VV 32000
#define TENC 64
#define STEPS 32
#define KOUT 2048   // 2*H

typedef unsigned long long ull;
typedef unsigned int u32;

// ---------------- scratch (device globals; no allocation allowed) ----------
__device__ float g_a0[BB * 192];
__device__ float g_h[BB * HH];            // fp32 master hidden state
__device__ float g_gi[BB * 3 * HH];
__device__ float g_gh[BB * 3 * HH];
__device__ float g_q[BB * HH];

// split-bf16 activations (16B-aligned for cp.async)
__device__ __align__(16) __nv_bfloat16 g_xh[BB * EE],  g_xl[BB * EE];
__device__ __align__(16) __nv_bfloat16 g_hbh[BB * HH], g_hbl[BB * HH];
__device__ __align__(16) __nv_bfloat16 g_vch[BB * KOUT], g_vcl[BB * KOUT];

// split-bf16 weights, all stored [N, K] row-major
__device__ __align__(16) __nv_bfloat16 g_Wihh[3 * HH * EE], g_Wihl[3 * HH * EE];
__device__ __align__(16) __nv_bfloat16 g_Whhh[3 * HH * HH], g_Whhl[3 * HH * HH];
__device__ __align__(16) __nv_bfloat16 g_Wah[HH * HH],      g_Wal[HH * HH];
__device__ __align__(16) __nv_bfloat16 g_Wouth[(size_t)VV * KOUT];
__device__ __align__(16) __nv_bfloat16 g_Woutl[(size_t)VV * KOUT];

// ====================== PTX helpers ========================================
__device__ __forceinline__ u32 smem_u32(const void* p) {
    u32 a;
    asm("{ .reg .u64 t; cvta.to.shared.u64 t, %1; cvt.u32.u64 %0, t; }"
        : "=r"(a) : "l"(p));
    return a;
}
__device__ __forceinline__ void cp16(u32 dst, const void* src) {
    asm volatile("cp.async.cg.shared.global [%0], [%1], 16;"
                 :: "r"(dst), "l"(src) : "memory");
}
__device__ __forceinline__ void cp_commit() {
    asm volatile("cp.async.commit_group;" ::: "memory");
}
__device__ __forceinline__ void cp_wait0() {
    asm volatile("cp.async.wait_group 0;" ::: "memory");
}
__device__ __forceinline__ void cp_wait1() {
    asm volatile("cp.async.wait_group 1;" ::: "memory");
}
__device__ __forceinline__ void ldmx4(u32* r, u32 addr) {
    asm volatile("ldmatrix.sync.aligned.m8n8.x4.shared.b16 {%0,%1,%2,%3}, [%4];"
                 : "=r"(r[0]), "=r"(r[1]), "=r"(r[2]), "=r"(r[3]) : "r"(addr));
}
__device__ __forceinline__ void mma16816(float* c, const u32* a, const u32* b) {
    asm volatile(
        "mma.sync.aligned.m16n8k16.row.col.f32.bf16.bf16.f32 "
        "{%0,%1,%2,%3}, {%4,%5,%6,%7}, {%8,%9}, {%0,%1,%2,%3};"
        : "+f"(c[0]), "+f"(c[1]), "+f"(c[2]), "+f"(c[3])
        : "r"(a[0]), "r"(a[1]), "r"(a[2]), "r"(a[3]), "r"(b[0]), "r"(b[1]));
}

// ===========================================================================
// Split-bf16 HMMA GEMM:
//   C[64, N] = (Ah+Al)[64,K] @ (Bh+Bl)[N,K]^T (+ bias)
//   = Ah·Bh + Al·Bh + Ah·Bl (Al·Bl dropped, ~2^-16 relative)
// CTA: 64 x 128 tile, 256 threads (8 warps, warp tile 32x32).
// K-chunks of 32, cp.async double-buffered. Requires N%128==0, K%32==0.
// ===========================================================================
#define LDAB 80          // padded SMEM row pitch in bytes (32 bf16 + 8 pad)
#define OFF_AH 0
#define OFF_AL 5120
#define OFF_BH 10240
#define OFF_BL 20480
#define BUFSZ  30720
#define GM_SMEM (2 * BUFSZ)   // 61440 bytes

__device__ __forceinline__ void load_chunk(
    u32 sb, const __nv_bfloat16* Ah, const __nv_bfloat16* Al,
    const __nv_bfloat16* Bh, const __nv_bfloat16* Bl,
    int n0, int K, int k0, int tid)
{
    // A: 64 rows x 32 k x {h,l} = 512 x 16B transfers
#pragma unroll
    for (int r = 0; r < 2; r++) {
        int i = tid + r * 256;
        int seg = i & 3, row = (i >> 2) & 63, hi = i >> 8;
        const __nv_bfloat16* src = (hi ? Al : Ah) + (size_t)row * K + k0 + seg * 8;
        cp16(sb + (hi ? OFF_AL : OFF_AH) + row * LDAB + seg * 16, src);
    }
    // B: 128 rows x 32 k x {h,l} = 1024 x 16B transfers
#pragma unroll
    for (int r = 0; r < 4; r++) {
        int i = tid + r * 256;
        int seg = i & 3, row = (i >> 2) & 127, hi = i >> 9;
        const __nv_bfloat16* src = (hi ? Bl : Bh) + (size_t)(n0 + row) * K + k0 + seg * 8;
        cp16(sb + (hi ? OFF_BL : OFF_BH) + row * LDAB + seg * 16, src);
    }
}

__global__ __launch_bounds__(256)
void gemm_mma(const __nv_bfloat16* __restrict__ Ah, const __nv_bfloat16* __restrict__ Al,
              const __nv_bfloat16* __restrict__ Bh, const __nv_bfloat16* __restrict__ Bl,
              const float* __restrict__ bias, float* __restrict__ C,
              long ldc, int N, int K)
{
    extern __shared__ char smem[];
    const u32 sb = smem_u32(smem);
    const int tid = threadIdx.x, wid = tid >> 5, lane = tid & 31;
    const int n_cta = blockIdx.x * 128;
    const int wm = (wid >> 2) * 32;   // warp m offset: 0 or 32
    const int wn = (wid & 3) * 32;    // warp n offset: 0,32,64,96

    float acc[2][4][4];
#pragma unroll
    for (int i = 0; i < 2; i++)
#pragma unroll
        for (int j = 0; j < 4; j++)
#pragma unroll
            for (int k = 0; k < 4; k++) acc[i][j][k] = 0.f;

    const int nk = K >> 5;   // K/32 chunks
    load_chunk(sb, Ah, Al, Bh, Bl, n_cta, K, 0, tid);
    cp_commit();

    // precomputed ldmatrix lane address components
    const int lrow = lane & 15;              // row within 16-row group
    const int lkof = (lane >> 4) * 16;       // 8 elems * 2B

    for (int i = 0; i < nk; i++) {
        const u32 bb = sb + (i & 1) * BUFSZ;
        if (i + 1 < nk) {
            load_chunk(sb + ((i + 1) & 1) * BUFSZ, Ah, Al, Bh, Bl,
                       n_cta, K, (i + 1) * 32, tid);
            cp_commit();
            cp_wait1();
        } else {
            cp_wait0();
        }
        __syncthreads();

#pragma unroll
        for (int ks = 0; ks < 2; ks++) {
            const u32 kb = ks * 32 + lkof;   // byte offset along k
            u32 ah[2][4], al[2][4], bh[2][4], bl[2][4];
            // A fragments: m tiles at wm, wm+16
            ldmx4(ah[0], bb + OFF_AH + (wm + lrow) * LDAB + kb);
            ldmx4(ah[1], bb + OFF_AH + (wm + 16 + lrow) * LDAB + kb);
            ldmx4(al[0], bb + OFF_AL + (wm + lrow) * LDAB + kb);
            ldmx4(al[1], bb + OFF_AL + (wm + 16 + lrow) * LDAB + kb);
            // B fragments: n tile pairs at wn, wn+16 (each x4 = two n8 tiles)
            ldmx4(bh[0], bb + OFF_BH + (wn + lrow) * LDAB + kb);
            ldmx4(bh[1], bb + OFF_BH + (wn + 16 + lrow) * LDAB + kb);
            ldmx4(bl[0], bb + OFF_BL + (wn + lrow) * LDAB + kb);
            ldmx4(bl[1], bb + OFF_BL + (wn + 16 + lrow) * LDAB + kb);

#pragma unroll
            for (int mt = 0; mt < 2; mt++) {
#pragma unroll
                for (int np = 0; np < 2; np++) {
                    // n8 tile 0 of pair: {r0, r2}; tile 1: {r1, r3}
                    u32 b0h[2] = { bh[np][0], bh[np][2] };
                    u32 b1h[2] = { bh[np][1], bh[np][3] };
                    u32 b0l[2] = { bl[np][0], bl[np][2] };
                    u32 b1l[2] = { bl[np][1], bl[np][3] };
                    float* c0 = acc[mt][np * 2];
                    float* c1 = acc[mt][np * 2 + 1];
                    mma16816(c0, ah[mt], b0h);
                    mma16816(c1, ah[mt], b1h);
                    mma16816(c0, al[mt], b0h);
                    mma16816(c1, al[mt], b1h);
                    mma16816(c0, ah[mt], b0l);
                    mma16816(c1, ah[mt], b1l);
                }
            }
        }
        __syncthreads();
    }

    // Epilogue: acc fragment (mt, nt): rows wm+mt*16+{t/4, t/4+8}, cols wn+nt*8+2*(t%4)
#pragma unroll
    for (int mt = 0; mt < 2; mt++) {
        int m = wm + mt * 16 + (lane >> 2);
#pragma unroll
        for (int nt = 0; nt < 4; nt++) {
            int n = n_cta + wn + nt * 8 + 2 * (lane & 3);
            float b0 = bias ? bias[n] : 0.f;
            float b1 = bias ? bias[n + 1] : 0.f;
            float2 v0 = { acc[mt][nt][0] + b0, acc[mt][nt][1] + b1 };
            float2 v1 = { acc[mt][nt][2] + b0, acc[mt][nt][3] + b1 };
            *reinterpret_cast<float2*>(C + (size_t)m * ldc + n) = v0;
            *reinterpret_cast<float2*>(C + (size_t)(m + 8) * ldc + n) = v1;
        }
    }
}

// ===================== weight conversion kernels ===========================
__device__ __forceinline__ void split2(float v, __nv_bfloat16& h, __nv_bfloat16& l) {
    h = __float2bfloat16(v);
    l = __float2bfloat16(v - __bfloat162float(h));
}

__global__ void esplit(const float* __restrict__ src,
                       __nv_bfloat16* __restrict__ dh, __nv_bfloat16* __restrict__ dl,
                       int n)
{
    int i = blockIdx.x * blockDim.x + threadIdx.x;
    if (i < n) split2(src[i], dh[i], dl[i]);
}

// transpose + split: src [K,N] fp32 -> dh/dl [N,K] bf16.  K,N % 32 == 0.
__global__ void tsplit(const float* __restrict__ src,
                       __nv_bfloat16* __restrict__ dh, __nv_bfloat16* __restrict__ dl,
                       int K, int N)
{
    __shared__ float t[32][33];
    int k0 = blockIdx.y * 32, n0 = blockIdx.x * 32;
    int tx = threadIdx.x, ty = threadIdx.y;   // 32 x 8
#pragma unroll
    for (int i = ty; i < 32; i += 8)
        t[i][tx] = src[(size_t)(k0 + i) * N + n0 + tx];
    __syncthreads();
#pragma unroll
    for (int i = ty; i < 32; i += 8) {
        float v = t[tx][i];
        __nv_bfloat16 h, l; split2(v, h, l);
        dh[(size_t)(n0 + i) * K + k0 + tx] = h;
        dl[(size_t)(n0 + i) * K + k0 + tx] = l;
    }
}

// ======================= small fp32 GEMM (init only) =======================
__global__ __launch_bounds__(128)
void gemm_init(const float* __restrict__ A, int lda,
               const float* __restrict__ Bm, const float* __restrict__ bias,
               float* __restrict__ C, int N, int K)
{
    __shared__ float As[16][68];
    __shared__ float Bs[16][132];
    const int tid = threadIdx.x;
    const int n0 = blockIdx.x * 128;
    const int tm = (tid >> 4) << 3, tn = (tid & 15) << 3;
    float acc[8][8] = {};
    for (int k0 = 0; k0 < K; k0 += 16) {
        {
            int k = tid & 15, m = tid >> 4;
#pragma unroll
            for (int i = 0; i < 8; i++)
                As[k][m + i * 8] = A[(m + i * 8) * lda + k0 + k];
        }
        {
            int w = tid >> 5, n4 = (tid & 31) << 2;
#pragma unroll
            for (int kb = 0; kb < 4; kb++) {
                int k = kb * 4 + w;
                *reinterpret_cast<float4*>(&Bs[k][n4]) =
                    *reinterpret_cast<const float4*>(&Bm[(size_t)(k0 + k) * N + n0 + n4]);
            }
        }
        __syncthreads();
#pragma unroll
        for (int kk = 0; kk < 16; kk++) {
#pragma unroll
            for (int i = 0; i < 8; i++) {
                float a = As[kk][tm + i];
#pragma unroll
                for (int j = 0; j < 8; j++) acc[i][j] += a * Bs[kk][tn + j];
            }
        }
        __syncthreads();
    }
#pragma unroll
    for (int i = 0; i < 8; i++)
#pragma unroll
        for (int j = 0; j < 8; j++) {
            int n = n0 + tn + j;
            C[(size_t)(tm + i) * N + n] = acc[i][j] + (bias ? bias[n] : 0.f);
        }
}

// ========================= per-step small kernels ==========================
__global__ void build_a0(const float* __restrict__ latent,
                         const int* __restrict__ style,
                         const float* __restrict__ style_emb)
{
    int idx = blockIdx.x * blockDim.x + threadIdx.x;
    if (idx >= BB * 192) return;
    int b = idx / 192, k = idx - b * 192;
    g_a0[idx] = (k < 128) ? latent[b * 128 + k]
                          : style_emb[style[b] * 64 + (k - 128)];
}

__global__ void init_x0(const float* __restrict__ emb)
{
    int idx = blockIdx.x * blockDim.x + threadIdx.x;   // 64*512
    float v = emb[EE /* BOS=1 row */ + (idx & (EE - 1))];
    split2(v, g_xh[idx], g_xl[idx]);
}

__global__ void conv_h()
{
    int idx = blockIdx.x * blockDim.x + threadIdx.x;   // 64*1024
    split2(g_h[idx], g_hbh[idx], g_hbl[idx]);
}

__global__ void gru_gates()
{
    int idx = blockIdx.x * blockDim.x + threadIdx.x;   // 64*1024
    int b = idx >> 10, j = idx & 1023;
    int base = b * 3 * HH + j;
    float ir = g_gi[base], iz = g_gi[base + HH], in = g_gi[base + 2 * HH];
    float hr = g_gh[base], hz = g_gh[base + HH], hn = g_gh[base + 2 * HH];
    float r = 1.f / (1.f + expf(-(ir + hr)));
    float z = 1.f / (1.f + expf(-(iz + hz)));
    float n = tanhf(in + r * hn);
    float hnew = (1.f - z) * n + z * g_h[idx];
    g_h[idx] = hnew;
    __nv_bfloat16 hh, hl; split2(hnew, hh, hl);
    g_hbh[idx] = hh; g_hbl[idx] = hl;
    g_vch[b * KOUT + j] = hh; g_vcl[b * KOUT + j] = hl;
}

__global__ void attn_kernel(const float* __restrict__ enc)
{
    int b = blockIdx.x;
    int tid = threadIdx.x;              // 256
    __shared__ float s_q[HH];
    __shared__ float s_scores[TENC];
    __shared__ float s_attn[TENC];

    for (int i = tid; i < HH; i += 256) s_q[i] = g_q[b * HH + i];
    __syncthreads();

    int warp = tid >> 5, lane = tid & 31;
    for (int t = warp; t < TENC; t += 8) {
        const float* e = enc + ((size_t)b * TENC + t) * HH;
        float s = 0.f;
        for (int h = lane; h < HH; h += 32) s += s_q[h] * e[h];
#pragma unroll
        for (int o = 16; o; o >>= 1) s += __shfl_xor_sync(0xFFFFFFFFu, s, o);
        if (lane == 0) s_scores[t] = s;
    }
    __syncthreads();

    float mx = -1e30f;
    for (int t = 0; t < TENC; t++) mx = fmaxf(mx, s_scores[t]);
    if (tid < TENC) s_attn[tid] = expf(s_scores[tid] - mx);
    __syncthreads();
    float ssum = 0.f;
    for (int t = 0; t < TENC; t++) ssum += s_attn[t];
    float inv = 1.f / ssum;

    for (int h = tid; h < HH; h += 256) {
        float c = 0.f;
        const float* eb = enc + (size_t)b * TENC * HH + h;
        for (int t = 0; t < TENC; t++) c += s_attn[t] * eb[(size_t)t * HH];
        c *= inv;
        __nv_bfloat16 ch, cl; split2(c, ch, cl);
        g_vch[b * KOUT + HH + h] = ch;
        g_vcl[b * KOUT + HH + h] = cl;
    }
}

__global__ void argmax_embed(const float* __restrict__ logits_t,
                             const float* __restrict__ emb)
{
    int b = blockIdx.x;
    int tid = threadIdx.x;              // 256
    const float* L = logits_t + (size_t)b * STEPS * VV;

    float best = -1e30f; int bi = VV;
    for (int n = tid; n < VV; n += 256) {
        float v = L[n];
        if (v > best) { best = v; bi = n; }
    }
    __shared__ float sv[256]; __shared__ int si[256];
    sv[tid] = best; si[tid] = bi;
    __syncthreads();
    for (int s = 128; s; s >>= 1) {
        if (tid < s) {
            if (sv[tid + s] > sv[tid] ||
                (sv[tid + s] == sv[tid] && si[tid + s] < si[tid])) {
                sv[tid] = sv[tid + s]; si[tid] = si[tid + s];
            }
        }
        __syncthreads();
    }
    int tok = si[0];
    for (int e = tid; e < EE; e += 256) {
        float v = emb[(size_t)tok * EE + e];
        split2(v, g_xh[b * EE + e], g_xl[b * EE + e]);
    }
}

// ===========================================================================
extern "C" void kernel_launch(void* const* d_in, const int* in_sizes, int n_in,
                              void* d_out, int out_size)
{
    const float* latent    = (const float*)d_in[0];
    const int*   style     = (const int*)  d_in[1];
    const float* enc       = (const float*)d_in[2];
    const float* emb       = (const float*)d_in[4];
    const float* style_emb = (const float*)d_in[5];
    const float* W_l2h     = (const float*)d_in[6];
    const float* b_l2h     = (const float*)d_in[7];
    const float* W_ih      = (const float*)d_in[8];
    const float* W_hh      = (const float*)d_in[9];
    const float* b_ih      = (const float*)d_in[10];
    const float* b_hh      = (const float*)d_in[11];
    const float* W_a       = (const float*)d_in[12];
    const float* W_out     = (const float*)d_in[13];
    const float* b_out     = (const float*)d_in[14];
    float* out = (float*)d_out;

    cudaFuncSetAttribute(gemm_mma, cudaFuncAttributeMaxDynamicSharedMemorySize, GM_SMEM);

    __nv_bfloat16 *pWihh, *pWihl, *pWhhh, *pWhhl, *pWah, *pWal, *pWouth, *pWoutl;
    __nv_bfloat16 *pxh, *pxl, *phbh, *phbl, *pvch, *pvcl;
    float *p_a0, *p_h, *p_gi, *p_gh, *p_q;
    cudaGetSymbolAddress((void**)&pWihh, g_Wihh);   cudaGetSymbolAddress((void**)&pWihl, g_Wihl);
    cudaGetSymbolAddress((void**)&pWhhh, g_Whhh);   cudaGetSymbolAddress((void**)&pWhhl, g_Whhl);
    cudaGetSymbolAddress((void**)&pWah,  g_Wah);    cudaGetSymbolAddress((void**)&pWal,  g_Wal);
    cudaGetSymbolAddress((void**)&pWouth, g_Wouth); cudaGetSymbolAddress((void**)&pWoutl, g_Woutl);
    cudaGetSymbolAddress((void**)&pxh,  g_xh);      cudaGetSymbolAddress((void**)&pxl,  g_xl);
    cudaGetSymbolAddress((void**)&phbh, g_hbh);     cudaGetSymbolAddress((void**)&phbl, g_hbl);
    cudaGetSymbolAddress((void**)&pvch, g_vch);     cudaGetSymbolAddress((void**)&pvcl, g_vcl);
    cudaGetSymbolAddress((void**)&p_a0, g_a0);
    cudaGetSymbolAddress((void**)&p_h,  g_h);
    cudaGetSymbolAddress((void**)&p_gi, g_gi);
    cudaGetSymbolAddress((void**)&p_gh, g_gh);
    cudaGetSymbolAddress((void**)&p_q,  g_q);

    // ---- weight conversion (per replay) ----
    esplit<<<(3 * HH * EE + 255) / 256, 256>>>(W_ih, pWihh, pWihl, 3 * HH * EE);
    esplit<<<(3 * HH * HH + 255) / 256, 256>>>(W_hh, pWhhh, pWhhl, 3 * HH * HH);
    tsplit<<<dim3(HH / 32, HH / 32), dim3(32, 8)>>>(W_a, pWah, pWal, HH, HH);
    tsplit<<<dim3(VV / 32, KOUT / 32), dim3(32, 8)>>>(W_out, pWouth, pWoutl, KOUT, VV);

    // ---- init ----
    build_a0<<<(BB * 192 + 255) / 256, 256>>>(latent, style, style_emb);
    init_x0<<<(BB * EE + 255) / 256, 256>>>(emb);
    gemm_init<<<HH / 128, 128>>>(p_a0, 192, W_l2h, b_l2h, p_h, HH, 192);
    conv_h<<<(BB * HH) / 256, 256>>>();

    // ---- decode loop ----
    for (int t = 0; t < STEPS; t++) {
        gemm_mma<<<3 * HH / 128, 256, GM_SMEM>>>(pxh, pxl, pWihh, pWihl, b_ih,
                                                 p_gi, 3 * HH, 3 * HH, EE);
        gemm_mma<<<3 * HH / 128, 256, GM_SMEM>>>(phbh, phbl, pWhhh, pWhhl, b_hh,
                                                 p_gh, 3 * HH, 3 * HH, HH);
        gru_gates<<<(BB * HH) / 256, 256>>>();
        gemm_mma<<<HH / 128, 256, GM_SMEM>>>(phbh, phbl, pWah, pWal, nullptr,
                                             p_q, HH, HH, HH);
        attn_kernel<<<BB, 256>>>(enc);
        gemm_mma<<<VV / 128, 256, GM_SMEM>>>(pvch, pvcl, pWouth, pWoutl, b_out,
                                             out + (size_t)t * VV, (long)STEPS * VV,
                                             VV, KOUT);
        if (t < STEPS - 1) argmax_embed<<<BB, 256>>>(out + (size_t)t * VV, emb);
    }
}

// round 6
// speedup vs baseline: 2.6615x; 1.0608x over previous
#include <cuda_runtime.h>
#include <cuda_bf16.h>
#include <math.h>

// Problem constants
#define BB 64
#define HH 1024
#define EE 512
#define VV 32000
#define TENC 64
#define STEPS 32
#define KOUT 2048   // 2*H

typedef unsigned long long ull;
typedef unsigned int u32;

// ---------------- scratch (device globals; no allocation allowed) ----------
__device__ float g_a0[BB * 192];
__device__ float g_h[BB * HH];            // fp32 master hidden state
__device__ float g_gi[BB * 3 * HH];
__device__ float g_gh[BB * 3 * HH];
__device__ float g_q[BB * HH];

// split-bf16 activations (16B-aligned for cp.async)
__device__ __align__(16) __nv_bfloat16 g_xh[BB * EE],  g_xl[BB * EE];
__device__ __align__(16) __nv_bfloat16 g_hbh[BB * HH], g_hbl[BB * HH];
__device__ __align__(16) __nv_bfloat16 g_vch[BB * KOUT], g_vcl[BB * KOUT];

// split-bf16 weights, all stored [N, K] row-major
__device__ __align__(16) __nv_bfloat16 g_Wihh[3 * HH * EE], g_Wihl[3 * HH * EE];
__device__ __align__(16) __nv_bfloat16 g_Whhh[3 * HH * HH], g_Whhl[3 * HH * HH];
__device__ __align__(16) __nv_bfloat16 g_Wah[HH * HH],      g_Wal[HH * HH];
__device__ __align__(16) __nv_bfloat16 g_Wouth[(size_t)VV * KOUT];
__device__ __align__(16) __nv_bfloat16 g_Woutl[(size_t)VV * KOUT];

// ====================== PTX helpers ========================================
__device__ __forceinline__ u32 smem_u32(const void* p) {
    u32 a;
    asm("{ .reg .u64 t; cvta.to.shared.u64 t, %1; cvt.u32.u64 %0, t; }"
        : "=r"(a) : "l"(p));
    return a;
}
__device__ __forceinline__ void cp16(u32 dst, const void* src) {
    asm volatile("cp.async.cg.shared.global [%0], [%1], 16;"
                 :: "r"(dst), "l"(src) : "memory");
}
__device__ __forceinline__ void cp_commit() {
    asm volatile("cp.async.commit_group;" ::: "memory");
}
__device__ __forceinline__ void cp_wait2() {
    asm volatile("cp.async.wait_group 2;" ::: "memory");
}
__device__ __forceinline__ void ldmx4(u32* r, u32 addr) {
    asm volatile("ldmatrix.sync.aligned.m8n8.x4.shared.b16 {%0,%1,%2,%3}, [%4];"
                 : "=r"(r[0]), "=r"(r[1]), "=r"(r[2]), "=r"(r[3]) : "r"(addr));
}
__device__ __forceinline__ void mma16816(float* c, const u32* a, const u32* b) {
    asm volatile(
        "mma.sync.aligned.m16n8k16.row.col.f32.bf16.bf16.f32 "
        "{%0,%1,%2,%3}, {%4,%5,%6,%7}, {%8,%9}, {%0,%1,%2,%3};"
        : "+f"(c[0]), "+f"(c[1]), "+f"(c[2]), "+f"(c[3])
        : "r"(a[0]), "r"(a[1]), "r"(a[2]), "r"(a[3]), "r"(b[0]), "r"(b[1]));
}

// ===========================================================================
// Split-bf16 HMMA GEMM body:
//   C[64, N] = (Ah+Al)[64,K] @ (Bh+Bl)[N,K]^T (+ bias)
//   = Ah·Bh + Al·Bh + Ah·Bl  (Al·Bl dropped, ~2^-16 relative)
// CTA tile 64 x NT (NT=128 or 256), 256 threads (8 warps, warp tile 32 x NT/4).
// K-chunks of 32, cp.async 3-stage pipeline. Requires K%32==0, K>=96.
// SMEM pitch 80B: 8-row ldmatrix phases hit all 32 banks exactly once.
// ===========================================================================
template <int NT>
__device__ __forceinline__ void load_chunk(
    u32 sb, const __nv_bfloat16* Ah, const __nv_bfloat16* Al,
    const __nv_bfloat16* Bh, const __nv_bfloat16* Bl,
    int n0, int K, int k0, int tid)
{
    const int OFF_AL = 64 * 80, OFF_BH = 128 * 80, OFF_BL = OFF_BH + NT * 80;
    // A: 64 rows x 32 k x {h,l} = 512 x 16B transfers
#pragma unroll
    for (int r = 0; r < 2; r++) {
        int i = tid + r * 256;
        int seg = i & 3, row = (i >> 2) & 63, hi = i >> 8;
        const __nv_bfloat16* src = (hi ? Al : Ah) + (size_t)row * K + k0 + seg * 8;
        cp16(sb + (hi ? OFF_AL : 0) + row * 80 + seg * 16, src);
    }
    // B: NT rows x 32 k x {h,l} = NT*8 x 16B transfers
#pragma unroll
    for (int r = 0; r < NT / 32; r++) {
        int i = tid + r * 256;
        int seg = i & 3, row = (i >> 2) & (NT - 1);
        int hi = (i >= NT * 4);
        const __nv_bfloat16* src = (hi ? Bl : Bh) + (size_t)(n0 + row) * K + k0 + seg * 8;
        cp16(sb + (hi ? OFF_BL : OFF_BH) + row * 80 + seg * 16, src);
    }
}

template <int NT>
__device__ __forceinline__ void gemm_body(
    const __nv_bfloat16* __restrict__ Ah, const __nv_bfloat16* __restrict__ Al,
    const __nv_bfloat16* __restrict__ Bh, const __nv_bfloat16* __restrict__ Bl,
    const float* __restrict__ bias, float* __restrict__ C,
    long ldc, int K, int n_cta, char* smem)
{
    const int BUFSZ = 80 * (128 + 2 * NT);
    const int OFF_BH = 128 * 80, OFF_BL = OFF_BH + NT * 80;
    const int NPW = NT / 4, NPAIR = NPW / 16;
    const u32 sb = smem_u32(smem);
    const int tid = threadIdx.x, wid = tid >> 5, lane = tid & 31;
    const int wm = (wid >> 2) * 32;      // warp m offset: 0 or 32
    const int wn = (wid & 3) * NPW;      // warp n offset

    float acc[2][2 * NPAIR][4] = {};

    const int nk = K >> 5;               // K/32 chunks (>= 3 for all shapes here)
    load_chunk<NT>(sb,          Ah, Al, Bh, Bl, n_cta, K, 0,  tid); cp_commit();
    load_chunk<NT>(sb + BUFSZ,  Ah, Al, Bh, Bl, n_cta, K, 32, tid); cp_commit();

    const int lrow = lane & 15;
    const int lkof = (lane >> 4) * 16;

    for (int i = 0; i < nk; i++) {
        if (i + 2 < nk)
            load_chunk<NT>(sb + ((i + 2) % 3) * BUFSZ, Ah, Al, Bh, Bl,
                           n_cta, K, (i + 2) * 32, tid);
        cp_commit();
        cp_wait2();          // chunk i's group complete (2 newer may be in flight)
        __syncthreads();

        const u32 bb = sb + (i % 3) * BUFSZ;
#pragma unroll
        for (int ks = 0; ks < 2; ks++) {
            const u32 kb = ks * 32 + lkof;
            u32 ah[2][4], al[2][4], bh[NPAIR][4], bl[NPAIR][4];
            ldmx4(ah[0], bb + (wm + lrow) * 80 + kb);
            ldmx4(ah[1], bb + (wm + 16 + lrow) * 80 + kb);
            ldmx4(al[0], bb + 5120 + (wm + lrow) * 80 + kb);
            ldmx4(al[1], bb + 5120 + (wm + 16 + lrow) * 80 + kb);
#pragma unroll
            for (int p = 0; p < NPAIR; p++) {
                ldmx4(bh[p], bb + OFF_BH + (wn + p * 16 + lrow) * 80 + kb);
                ldmx4(bl[p], bb + OFF_BL + (wn + p * 16 + lrow) * 80 + kb);
            }
#pragma unroll
            for (int mt = 0; mt < 2; mt++) {
#pragma unroll
                for (int p = 0; p < NPAIR; p++) {
                    u32 b0h[2] = { bh[p][0], bh[p][2] };
                    u32 b1h[2] = { bh[p][1], bh[p][3] };
                    u32 b0l[2] = { bl[p][0], bl[p][2] };
                    u32 b1l[2] = { bl[p][1], bl[p][3] };
                    float* c0 = acc[mt][p * 2];
                    float* c1 = acc[mt][p * 2 + 1];
                    mma16816(c0, ah[mt], b0h);
                    mma16816(c1, ah[mt], b1h);
                    mma16816(c0, al[mt], b0h);
                    mma16816(c1, al[mt], b1h);
                    mma16816(c0, ah[mt], b0l);
                    mma16816(c1, ah[mt], b1l);
                }
            }
        }
        __syncthreads();
    }

    // Epilogue: frag (mt, p, t): rows wm+mt*16+{l/4, l/4+8}, cols wn+p*16+t*8+2*(l%4)
#pragma unroll
    for (int mt = 0; mt < 2; mt++) {
        int m = wm + mt * 16 + (lane >> 2);
#pragma unroll
        for (int p = 0; p < NPAIR; p++) {
#pragma unroll
            for (int t = 0; t < 2; t++) {
                int n = n_cta + wn + p * 16 + t * 8 + 2 * (lane & 3);
                float* a = acc[mt][p * 2 + t];
                float b0 = bias ? bias[n] : 0.f;
                float b1 = bias ? bias[n + 1] : 0.f;
                float2 v0 = { a[0] + b0, a[1] + b1 };
                float2 v1 = { a[2] + b0, a[3] + b1 };
                *reinterpret_cast<float2*>(C + (size_t)m * ldc + n) = v0;
                *reinterpret_cast<float2*>(C + (size_t)(m + 8) * ldc + n) = v1;
            }
        }
    }
}

template <int NT>
__global__ __launch_bounds__(256)
void gemm_k(const __nv_bfloat16* __restrict__ Ah, const __nv_bfloat16* __restrict__ Al,
            const __nv_bfloat16* __restrict__ Bh, const __nv_bfloat16* __restrict__ Bl,
            const float* __restrict__ bias, float* __restrict__ C,
            long ldc, int K)
{
    extern __shared__ char smem[];
    gemm_body<NT>(Ah, Al, Bh, Bl, bias, C, ldc, K, blockIdx.x * NT, smem);
}

// fused gi + gh: blocks 0..23 -> gi = x @ W_ih^T, blocks 24..47 -> gh = h @ W_hh^T
__global__ __launch_bounds__(256)
void gemm_gigh(const __nv_bfloat16* __restrict__ xh, const __nv_bfloat16* __restrict__ xl,
               const __nv_bfloat16* __restrict__ Wihh, const __nv_bfloat16* __restrict__ Wihl,
               const float* __restrict__ b_ih, float* __restrict__ gi,
               const __nv_bfloat16* __restrict__ hbh, const __nv_bfloat16* __restrict__ hbl,
               const __nv_bfloat16* __restrict__ Whhh, const __nv_bfloat16* __restrict__ Whhl,
               const float* __restrict__ b_hh, float* __restrict__ gh)
{
    extern __shared__ char smem[];
    if (blockIdx.x < 24)
        gemm_body<128>(xh, xl, Wihh, Wihl, b_ih, gi, 3 * HH, EE,
                       blockIdx.x * 128, smem);
    else
        gemm_body<128>(hbh, hbl, Whhh, Whhl, b_hh, gh, 3 * HH, HH,
                       (blockIdx.x - 24) * 128, smem);
}

#define SMEM_128 (3 * 80 * (128 + 2 * 128))   //  92160
#define SMEM_256 (3 * 80 * (128 + 2 * 256))   // 153600

// ===================== weight conversion kernels ===========================
__device__ __forceinline__ void split2(float v, __nv_bfloat16& h, __nv_bfloat16& l) {
    h = __float2bfloat16(v);
    l = __float2bfloat16(v - __bfloat162float(h));
}

__global__ void esplit(const float* __restrict__ src,
                       __nv_bfloat16* __restrict__ dh, __nv_bfloat16* __restrict__ dl,
                       int n)
{
    int i = blockIdx.x * blockDim.x + threadIdx.x;
    if (i < n) split2(src[i], dh[i], dl[i]);
}

// transpose + split: src [K,N] fp32 -> dh/dl [N,K] bf16.  K,N % 32 == 0.
__global__ void tsplit(const float* __restrict__ src,
                       __nv_bfloat16* __restrict__ dh, __nv_bfloat16* __restrict__ dl,
                       int K, int N)
{
    __shared__ float t[32][33];
    int k0 = blockIdx.y * 32, n0 = blockIdx.x * 32;
    int tx = threadIdx.x, ty = threadIdx.y;   // 32 x 8
#pragma unroll
    for (int i = ty; i < 32; i += 8)
        t[i][tx] = src[(size_t)(k0 + i) * N + n0 + tx];
    __syncthreads();
#pragma unroll
    for (int i = ty; i < 32; i += 8) {
        float v = t[tx][i];
        __nv_bfloat16 h, l; split2(v, h, l);
        dh[(size_t)(n0 + i) * K + k0 + tx] = h;
        dl[(size_t)(n0 + i) * K + k0 + tx] = l;
    }
}

// ======================= small fp32 GEMM (init only) =======================
__global__ __launch_bounds__(128)
void gemm_init(const float* __restrict__ A, int lda,
               const float* __restrict__ Bm, const float* __restrict__ bias,
               float* __restrict__ C, int N, int K)
{
    __shared__ float As[16][68];
    __shared__ float Bs[16][132];
    const int tid = threadIdx.x;
    const int n0 = blockIdx.x * 128;
    const int tm = (tid >> 4) << 3, tn = (tid & 15) << 3;
    float acc[8][8] = {};
    for (int k0 = 0; k0 < K; k0 += 16) {
        {
            int k = tid & 15, m = tid >> 4;
#pragma unroll
            for (int i = 0; i < 8; i++)
                As[k][m + i * 8] = A[(m + i * 8) * lda + k0 + k];
        }
        {
            int w = tid >> 5, n4 = (tid & 31) << 2;
#pragma unroll
            for (int kb = 0; kb < 4; kb++) {
                int k = kb * 4 + w;
                *reinterpret_cast<float4*>(&Bs[k][n4]) =
                    *reinterpret_cast<const float4*>(&Bm[(size_t)(k0 + k) * N + n0 + n4]);
            }
        }
        __syncthreads();
#pragma unroll
        for (int kk = 0; kk < 16; kk++) {
#pragma unroll
            for (int i = 0; i < 8; i++) {
                float a = As[kk][tm + i];
#pragma unroll
                for (int j = 0; j < 8; j++) acc[i][j] += a * Bs[kk][tn + j];
            }
        }
        __syncthreads();
    }
#pragma unroll
    for (int i = 0; i < 8; i++)
#pragma unroll
        for (int j = 0; j < 8; j++) {
            int n = n0 + tn + j;
            C[(size_t)(tm + i) * N + n] = acc[i][j] + (bias ? bias[n] : 0.f);
        }
}

// ========================= per-step small kernels ==========================
__global__ void build_a0(const float* __restrict__ latent,
                         const int* __restrict__ style,
                         const float* __restrict__ style_emb)
{
    int idx = blockIdx.x * blockDim.x + threadIdx.x;
    if (idx >= BB * 192) return;
    int b = idx / 192, k = idx - b * 192;
    g_a0[idx] = (k < 128) ? latent[b * 128 + k]
                          : style_emb[style[b] * 64 + (k - 128)];
}

__global__ void init_x0(const float* __restrict__ emb)
{
    int idx = blockIdx.x * blockDim.x + threadIdx.x;   // 64*512
    float v = emb[EE /* BOS=1 row */ + (idx & (EE - 1))];
    split2(v, g_xh[idx], g_xl[idx]);
}

__global__ void conv_h()
{
    int idx = blockIdx.x * blockDim.x + threadIdx.x;   // 64*1024
    split2(g_h[idx], g_hbh[idx], g_hbl[idx]);
}

__global__ void gru_gates()
{
    int idx = blockIdx.x * blockDim.x + threadIdx.x;   // 64*1024
    int b = idx >> 10, j = idx & 1023;
    int base = b * 3 * HH + j;
    float ir = g_gi[base], iz = g_gi[base + HH], in = g_gi[base + 2 * HH];
    float hr = g_gh[base], hz = g_gh[base + HH], hn = g_gh[base + 2 * HH];
    float r = 1.f / (1.f + expf(-(ir + hr)));
    float z = 1.f / (1.f + expf(-(iz + hz)));
    float n = tanhf(in + r * hn);
    float hnew = (1.f - z) * n + z * g_h[idx];
    g_h[idx] = hnew;
    __nv_bfloat16 hh, hl; split2(hnew, hh, hl);
    g_hbh[idx] = hh; g_hbl[idx] = hl;
    g_vch[b * KOUT + j] = hh; g_vcl[b * KOUT + j] = hl;
}

__global__ void attn_kernel(const float* __restrict__ enc)
{
    int b = blockIdx.x;
    int tid = threadIdx.x;              // 256
    __shared__ float s_q[HH];
    __shared__ float s_scores[TENC];
    __shared__ float s_attn[TENC];

    for (int i = tid; i < HH; i += 256) s_q[i] = g_q[b * HH + i];
    __syncthreads();

    int warp = tid >> 5, lane = tid & 31;
    for (int t = warp; t < TENC; t += 8) {
        const float* e = enc + ((size_t)b * TENC + t) * HH;
        float s = 0.f;
        for (int h = lane; h < HH; h += 32) s += s_q[h] * e[h];
#pragma unroll
        for (int o = 16; o; o >>= 1) s += __shfl_xor_sync(0xFFFFFFFFu, s, o);
        if (lane == 0) s_scores[t] = s;
    }
    __syncthreads();

    float mx = -1e30f;
    for (int t = 0; t < TENC; t++) mx = fmaxf(mx, s_scores[t]);
    if (tid < TENC) s_attn[tid] = expf(s_scores[tid] - mx);
    __syncthreads();
    float ssum = 0.f;
    for (int t = 0; t < TENC; t++) ssum += s_attn[t];
    float inv = 1.f / ssum;

    for (int h = tid; h < HH; h += 256) {
        float c = 0.f;
        const float* eb = enc + (size_t)b * TENC * HH + h;
        for (int t = 0; t < TENC; t++) c += s_attn[t] * eb[(size_t)t * HH];
        c *= inv;
        __nv_bfloat16 ch, cl; split2(c, ch, cl);
        g_vch[b * KOUT + HH + h] = ch;
        g_vcl[b * KOUT + HH + h] = cl;
    }
}

__global__ void argmax_embed(const float* __restrict__ logits_t,
                             const float* __restrict__ emb)
{
    int b = blockIdx.x;
    int tid = threadIdx.x;              // 256
    const float* L = logits_t + (size_t)b * STEPS * VV;

    float best = -1e30f; int bi = VV;
    for (int n = tid; n < VV; n += 256) {
        float v = L[n];
        if (v > best) { best = v; bi = n; }
    }
    __shared__ float sv[256]; __shared__ int si[256];
    sv[tid] = best; si[tid] = bi;
    __syncthreads();
    for (int s = 128; s; s >>= 1) {
        if (tid < s) {
            if (sv[tid + s] > sv[tid] ||
                (sv[tid + s] == sv[tid] && si[tid + s] < si[tid])) {
                sv[tid] = sv[tid + s]; si[tid] = si[tid + s];
            }
        }
        __syncthreads();
    }
    int tok = si[0];
    for (int e = tid; e < EE; e += 256) {
        float v = emb[(size_t)tok * EE + e];
        split2(v, g_xh[b * EE + e], g_xl[b * EE + e]);
    }
}

// ===========================================================================
extern "C" void kernel_launch(void* const* d_in, const int* in_sizes, int n_in,
                              void* d_out, int out_size)
{
    const float* latent    = (const float*)d_in[0];
    const int*   style     = (const int*)  d_in[1];
    const float* enc       = (const float*)d_in[2];
    const float* emb       = (const float*)d_in[4];
    const float* style_emb = (const float*)d_in[5];
    const float* W_l2h     = (const float*)d_in[6];
    const float* b_l2h     = (const float*)d_in[7];
    const float* W_ih      = (const float*)d_in[8];
    const float* W_hh      = (const float*)d_in[9];
    const float* b_ih      = (const float*)d_in[10];
    const float* b_hh      = (const float*)d_in[11];
    const float* W_a       = (const float*)d_in[12];
    const float* W_out     = (const float*)d_in[13];
    const float* b_out     = (const float*)d_in[14];
    float* out = (float*)d_out;

    cudaFuncSetAttribute(gemm_k<128>, cudaFuncAttributeMaxDynamicSharedMemorySize, SMEM_128);
    cudaFuncSetAttribute(gemm_k<256>, cudaFuncAttributeMaxDynamicSharedMemorySize, SMEM_256);
    cudaFuncSetAttribute(gemm_gigh,   cudaFuncAttributeMaxDynamicSharedMemorySize, SMEM_128);

    __nv_bfloat16 *pWihh, *pWihl, *pWhhh, *pWhhl, *pWah, *pWal, *pWouth, *pWoutl;
    __nv_bfloat16 *pxh, *pxl, *phbh, *phbl, *pvch, *pvcl;
    float *p_a0, *p_h, *p_gi, *p_gh, *p_q;
    cudaGetSymbolAddress((void**)&pWihh, g_Wihh);   cudaGetSymbolAddress((void**)&pWihl, g_Wihl);
    cudaGetSymbolAddress((void**)&pWhhh, g_Whhh);   cudaGetSymbolAddress((void**)&pWhhl, g_Whhl);
    cudaGetSymbolAddress((void**)&pWah,  g_Wah);    cudaGetSymbolAddress((void**)&pWal,  g_Wal);
    cudaGetSymbolAddress((void**)&pWouth, g_Wouth); cudaGetSymbolAddress((void**)&pWoutl, g_Woutl);
    cudaGetSymbolAddress((void**)&pxh,  g_xh);      cudaGetSymbolAddress((void**)&pxl,  g_xl);
    cudaGetSymbolAddress((void**)&phbh, g_hbh);     cudaGetSymbolAddress((void**)&phbl, g_hbl);
    cudaGetSymbolAddress((void**)&pvch, g_vch);     cudaGetSymbolAddress((void**)&pvcl, g_vcl);
    cudaGetSymbolAddress((void**)&p_a0, g_a0);
    cudaGetSymbolAddress((void**)&p_h,  g_h);
    cudaGetSymbolAddress((void**)&p_gi, g_gi);
    cudaGetSymbolAddress((void**)&p_gh, g_gh);
    cudaGetSymbolAddress((void**)&p_q,  g_q);

    // ---- weight conversion (per replay) ----
    esplit<<<(3 * HH * EE + 255) / 256, 256>>>(W_ih, pWihh, pWihl, 3 * HH * EE);
    esplit<<<(3 * HH * HH + 255) / 256, 256>>>(W_hh, pWhhh, pWhhl, 3 * HH * HH);
    tsplit<<<dim3(HH / 32, HH / 32), dim3(32, 8)>>>(W_a, pWah, pWal, HH, HH);
    tsplit<<<dim3(VV / 32, KOUT / 32), dim3(32, 8)>>>(W_out, pWouth, pWoutl, KOUT, VV);

    // ---- init ----
    build_a0<<<(BB * 192 + 255) / 256, 256>>>(latent, style, style_emb);
    init_x0<<<(BB * EE + 255) / 256, 256>>>(emb);
    gemm_init<<<HH / 128, 128>>>(p_a0, 192, W_l2h, b_l2h, p_h, HH, 192);
    conv_h<<<(BB * HH) / 256, 256>>>();

    // ---- decode loop ----
    for (int t = 0; t < STEPS; t++) {
        gemm_gigh<<<48, 256, SMEM_128>>>(pxh, pxl, pWihh, pWihl, b_ih, p_gi,
                                         phbh, phbl, pWhhh, pWhhl, b_hh, p_gh);
        gru_gates<<<(BB * HH) / 256, 256>>>();
        gemm_k<128><<<HH / 128, 256, SMEM_128>>>(phbh, phbl, pWah, pWal, nullptr,
                                                 p_q, HH, HH);
        attn_kernel<<<BB, 256>>>(enc);
        gemm_k<256><<<VV / 256, 256, SMEM_256>>>(pvch, pvcl, pWouth, pWoutl, b_out,
                                                 out + (size_t)t * VV, (long)STEPS * VV,
                                                 KOUT);
        if (t < STEPS - 1) argmax_embed<<<BB, 256>>>(out + (size_t)t * VV, emb);
    }
}